// round 5
// baseline (speedup 1.0000x reference)
#include <cuda_runtime.h>
#include <cfloat>
#include <cstdint>

// Problem geometry (fixed by the reference): planes of 128x128, B*C planes.
constexpr int W_DIM       = 128;
constexpr int HW          = 128 * 128;   // 16384 elements per (b,c) plane
constexpr int THREADS     = 1024;
constexpr int V4          = HW / 4;      // 4096 float4 per plane
constexpr int PER         = V4 / THREADS;// 4 float4 per thread
constexpr int PLANE_BYTES = HW * 4;      // 65536
constexpr int SMEM_BYTES  = 2 * PLANE_BYTES;

__device__ __forceinline__ float warp_sum(float v) {
    #pragma unroll
    for (int o = 16; o > 0; o >>= 1) v += __shfl_down_sync(0xffffffffu, v, o);
    return v;
}
__device__ __forceinline__ float warp_min(float v) {
    #pragma unroll
    for (int o = 16; o > 0; o >>= 1) v = fminf(v, __shfl_down_sync(0xffffffffu, v, o));
    return v;
}
__device__ __forceinline__ float warp_max(float v) {
    #pragma unroll
    for (int o = 16; o > 0; o >>= 1) v = fmaxf(v, __shfl_down_sync(0xffffffffu, v, o));
    return v;
}

__device__ __forceinline__ uint32_t smem_u32(const void* p) {
    uint32_t a;
    asm("{ .reg .u64 t; cvta.to.shared.u64 t, %1; cvt.u32.u64 %0, t; }" : "=r"(a) : "l"(p));
    return a;
}

__device__ __forceinline__ void mbar_init(uint32_t mb, uint32_t cnt) {
    asm volatile("mbarrier.init.shared.b64 [%0], %1;" :: "r"(mb), "r"(cnt) : "memory");
}
__device__ __forceinline__ void tma_1d_load(uint32_t smem_dst, const void* gmem_src,
                                            uint32_t bytes, uint32_t mb) {
    asm volatile("mbarrier.arrive.expect_tx.shared.b64 _, [%0], %1;"
                 :: "r"(mb), "r"(bytes) : "memory");
    asm volatile("cp.async.bulk.shared::cluster.global.mbarrier::complete_tx::bytes "
                 "[%0], [%1], %2, [%3];"
                 :: "r"(smem_dst), "l"(gmem_src), "r"(bytes), "r"(mb) : "memory");
}
__device__ __forceinline__ void mbar_wait(uint32_t mb, uint32_t parity) {
    uint32_t done;
    asm volatile("{\n\t.reg .pred p;\n\t"
                 "mbarrier.try_wait.parity.acquire.cta.shared::cta.b64 p, [%1], %2;\n\t"
                 "selp.b32 %0, 1, 0, p;\n\t}"
                 : "=r"(done) : "r"(mb), "r"(parity) : "memory");
    if (!done) {
        asm volatile("{\n\t.reg .pred P1;\n\t"
                     "W%=:\n\t"
                     "mbarrier.try_wait.parity.acquire.cta.shared::cta.b64 P1, [%0], %1, 0x989680;\n\t"
                     "@P1 bra.uni D%=;\n\t"
                     "bra.uni W%=;\n\t"
                     "D%=:\n\t}"
                     :: "r"(mb), "r"(parity) : "memory");
    }
}

extern __shared__ float4 sbuf[];   // 2 planes: [2][V4]

__global__ __launch_bounds__(THREADS, 1)
void hm2kp_kernel(const float* __restrict__ in,
                  float* __restrict__ map_out,
                  float* __restrict__ kp_out,
                  float* __restrict__ zeta_out,
                  int planes)
{
    __shared__ float s_r0[32], s_r1[32], s_r2[32];
    __shared__ float s_bmin, s_rcp;
    __shared__ alignas(8) uint64_t mbar_store[2];

    const int tid    = threadIdx.x;
    const int lane   = tid & 31;
    const int wid    = tid >> 5;
    const int stride = gridDim.x;

    const uint32_t mb[2] = { smem_u32(&mbar_store[0]), smem_u32(&mbar_store[1]) };
    const uint32_t sb[2] = { smem_u32(&sbuf[0]), smem_u32(&sbuf[0]) + (uint32_t)PLANE_BYTES };

    if (tid == 0) { mbar_init(mb[0], 1); mbar_init(mb[1], 1); }
    __syncthreads();

    // Prologue: issue TMA loads for the first two planes (decoupled read stream).
    const int p0 = blockIdx.x;
    if (tid == 0) {
        if (p0 < planes)
            tma_1d_load(sb[0], in + (size_t)p0 * HW, PLANE_BYTES, mb[0]);
        if (p0 + stride < planes)
            tma_1d_load(sb[1], in + (size_t)(p0 + stride) * HW, PLANE_BYTES, mb[1]);
    }

    int k = 0;
    for (int p = p0; p < planes; p += stride, ++k) {
        const int buf = k & 1;
        const uint32_t parity = (uint32_t)(k >> 1) & 1u;   // n-th reuse of this buffer

        // Wait for this plane's TMA completion (acquire orders the LDS below).
        mbar_wait(mb[buf], parity);

        // ---- Stage smem plane into registers; raw min/max ----
        const float4* __restrict__ sp = sbuf + buf * V4;
        float4 v[PER];
        float lmin = FLT_MAX, lmax = -FLT_MAX;
        #pragma unroll
        for (int i = 0; i < PER; ++i) {
            v[i] = sp[tid + i * THREADS];
            lmin = fminf(lmin, fminf(fminf(v[i].x, v[i].y), fminf(v[i].z, v[i].w)));
            lmax = fmaxf(lmax, fmaxf(fmaxf(v[i].x, v[i].y), fmaxf(v[i].z, v[i].w)));
        }

        // ---- Block reduce min/max (32 warps) ----
        lmin = warp_min(lmin);
        lmax = warp_max(lmax);
        if (lane == 0) { s_r0[wid] = lmin; s_r1[wid] = lmax; }
        __syncthreads();   // <- all threads now hold their data in regs; smem reusable

        // Refill this buffer with plane p + 2*stride (issued from warp 1 so it
        // doesn't serialize with warp 0's final reduce).
        if (tid == 32) {
            const int pn = p + 2 * stride;
            if (pn < planes)
                tma_1d_load(sb[buf], in + (size_t)pn * HW, PLANE_BYTES, mb[buf]);
        }
        if (wid == 0) {
            float m0 = warp_min(s_r0[lane]);
            float m1 = warp_max(s_r1[lane]);
            if (lane == 0) { s_bmin = m0; s_rcp = 1.0f / m1; }  // ref divides by max
        }
        __syncthreads();

        const float bmin = s_bmin;
        const float rcp  = s_rcp;

        // ---- Normalize, store, accumulate sums on NORMALIZED values ----
        float4* __restrict__ op = reinterpret_cast<float4*>(map_out) + (size_t)p * V4;
        float sum = 0.f, sx = 0.f, sy = 0.f;
        #pragma unroll
        for (int i = 0; i < PER; ++i) {
            const int i4 = tid + i * THREADS;
            const float m0 = (v[i].x - bmin) * rcp;
            const float m1 = (v[i].y - bmin) * rcp;
            const float m2 = (v[i].z - bmin) * rcp;
            const float m3 = (v[i].w - bmin) * rcp;

            const int base = i4 << 2;
            const float x0 = (float)(base & (W_DIM - 1));
            const float yy = (float)(base >> 7);

            const float s4 = (m0 + m1) + (m2 + m3);
            sum += s4;
            sx  += m0 * x0 + m1 * (x0 + 1.f) + m2 * (x0 + 2.f) + m3 * (x0 + 3.f);
            sy  += s4 * yy;

            __stcs(&op[i4], make_float4(m0, m1, m2, m3));
        }

        // ---- Block reduce the three sums ----
        sum = warp_sum(sum);
        sx  = warp_sum(sx);
        sy  = warp_sum(sy);
        if (lane == 0) { s_r0[wid] = sum; s_r1[wid] = sx; s_r2[wid] = sy; }
        __syncthreads();
        if (wid == 0) {
            float a = warp_sum(s_r0[lane]);
            float b = warp_sum(s_r1[lane]);
            float c = warp_sum(s_r2[lane]);
            if (lane == 0) {
                kp_out[(size_t)p * 2 + 0] = rintf(b / a);  // round(get_kp_x / zeta)
                kp_out[(size_t)p * 2 + 1] = rintf(c / a);  // round(get_kp_y / zeta)
                zeta_out[p] = a;
            }
        }
        __syncthreads();
    }
}

extern "C" void kernel_launch(void* const* d_in, const int* in_sizes, int n_in,
                              void* d_out, int out_size)
{
    const float* in = (const float*)d_in[0];
    const int total  = in_sizes[0];        // B*C*H*W
    const int planes = total / HW;         // B*C = 6400

    float* map  = (float*)d_out;                       // [B,C,H,W]
    float* kp   = map + (size_t)total;                 // [B,C,2]
    float* zeta = kp + (size_t)planes * 2;             // [B,C]

    int dev = 0, sms = 148;
    cudaGetDevice(&dev);
    cudaDeviceGetAttribute(&sms, cudaDevAttrMultiProcessorCount, dev);

    static bool attr_set = false;
    if (!attr_set) {
        cudaFuncSetAttribute(hm2kp_kernel,
                             cudaFuncAttributeMaxDynamicSharedMemorySize, SMEM_BYTES);
        attr_set = true;
    }

    hm2kp_kernel<<<sms, THREADS, SMEM_BYTES>>>(in, map, kp, zeta, planes);
}